// round 6
// baseline (speedup 1.0000x reference)
#include <cuda_runtime.h>
#include <cuda_bf16.h>

// Shapes (fixed): char_feats [L=512, B=256, D=256] f32 (time-major),
// word_ids/attention_mask [B, L] i32, out = [W=128,B,D] f32 ++ [W,B] f32
#define Lc 512
#define Bc 256
#define Dc 256
#define Wc 128
#define CH 64                 // rows per pool chunk
#define NCH (Lc / CH)         // 8 chunks

__device__ int g_char_num[Bc];        // sum(mask) - 2
__device__ int g_winfo[Bc][Wc];       // lo | (cnt << 16), clipped to [1,cap)

// ---------------------------------------------------------------------------
// prep: per batch row — run starts, clipped per-word [lo,cnt], masks, and
// zero-fill of every word slot that is NOT written by a single-chunk store
// (boundary-spanning words get accumulated via atomicAdd; invalid/empty words
// keep the zero as final value).
// ---------------------------------------------------------------------------
__global__ void prep_kernel(const int* __restrict__ word_ids,
                            const int* __restrict__ attn,
                            float4* __restrict__ out,
                            float* __restrict__ mask_out) {
    const int b = blockIdx.x;
    const int t = threadIdx.x;  // 512 == L

    __shared__ int s_ids[Lc];
    __shared__ int s_starts[Wc + 1];
    __shared__ int s_red[16];
    __shared__ unsigned char s_zero[Wc];
    __shared__ int s_cap, s_wn;

    const int wid = word_ids[b * Lc + t];
    s_ids[t] = wid;
    int m = attn[b * Lc + t];

    if (t <= Wc) s_starts[t] = Lc;
    __syncthreads();

    if (t == 0 || s_ids[t] != s_ids[t - 1]) s_starts[wid] = t;

    #pragma unroll
    for (int o = 16; o > 0; o >>= 1) m += __shfl_down_sync(0xffffffffu, m, o);
    if ((t & 31) == 0) s_red[t >> 5] = m;
    __syncthreads();
    if (t < 16) {
        int v = s_red[t];
        #pragma unroll
        for (int o = 8; o > 0; o >>= 1) v += __shfl_down_sync(0xffffu, v, o);
        if (t == 0) {
            g_char_num[b] = v - 2;        // *** the R4 bug: this write was missing ***
            s_cap = (v - 2) + 1;          // valid l in [1, cap)
            s_wn  = s_ids[Lc - 1] + 1;
        }
    }
    __syncthreads();

    const int cap = s_cap, wn = s_wn;
    if (t < Wc) {
        int s = s_starts[t], e = s_starts[t + 1];
        int lo = min(max(s, 1), cap);
        int hi = min(max(e, 1), cap);
        int cnt = hi - lo; if (cnt < 0) cnt = 0;
        const bool valid = (t < wn) && (cnt > 0);
        const bool interior = valid && ((lo / CH) == ((hi - 1) / CH));
        g_winfo[b][t] = lo | (cnt << 16);
        s_zero[t] = interior ? 0 : 1;
        mask_out[t * Bc + b] = (t < wn) ? 1.0f : 0.0f;
    }
    __syncthreads();

    // zero-fill non-interior word slots: warp per word, strided
    const int warp = t >> 5, lane = t & 31;
    const float4 zero = make_float4(0.f, 0.f, 0.f, 0.f);
    for (int w = warp; w < Wc; w += 16) {
        if (s_zero[w]) {
            float4* o = out + ((size_t)w * Bc + b) * (Dc / 4);
            o[lane] = zero;
            o[lane + 32] = zero;
        }
    }
}

// ---------------------------------------------------------------------------
// pool: grid (NCH, B), 64 threads (one float4 lane over D each). Each block
// sweeps 64 consecutive l-rows of one batch row with an 8-deep prefetch ring.
// Word fully inside the chunk -> plain store of mean; spanning -> atomicAdd
// of partial mean into the pre-zeroed slot.
// ---------------------------------------------------------------------------
__global__ __launch_bounds__(64) void pool_kernel(
    const float4* __restrict__ cf,       // [L, B, D/4]
    const int* __restrict__ word_ids,    // [B, L]
    float4* __restrict__ out)            // [W, B, D/4]
{
    const int t = threadIdx.x;           // float4 lane over D
    const int c = blockIdx.x;
    const int b = blockIdx.y;

    const int cap  = 1 + g_char_num[b];
    const int base = c * CH;
    int r0 = base;      if (r0 < 1)   r0 = 1;
    int r1 = base + CH; if (r1 > cap) r1 = cap;

    __shared__ int s_wid[CH];
    {
        const int l = base + t;          // t < 64 == CH
        s_wid[t] = (l >= r0 && l < r1) ? word_ids[b * Lc + l] : -1;
    }
    __syncthreads();
    if (r0 >= r1) return;

    const int n    = r1 - r0;
    const int sidx = r0 - base;          // shared offset of row r0
    const size_t stride = (size_t)Bc * (Dc / 4);
    const float4* p = cf + ((size_t)r0 * Bc + b) * (Dc / 4) + t;

    const float4 zero = make_float4(0.f, 0.f, 0.f, 0.f);

    // prime 8-deep ring
    float4 q0 = zero, q1 = zero, q2 = zero, q3 = zero;
    float4 q4 = zero, q5 = zero, q6 = zero, q7 = zero;
    if (0 < n) q0 = p[0 * stride];
    if (1 < n) q1 = p[1 * stride];
    if (2 < n) q2 = p[2 * stride];
    if (3 < n) q3 = p[3 * stride];
    if (4 < n) q4 = p[4 * stride];
    if (5 < n) q5 = p[5 * stride];
    if (6 < n) q6 = p[6 * stride];
    if (7 < n) q7 = p[7 * stride];
    int lpf = 8;

    float4 acc = zero;
    int i = 0;

#define STEP(P)                                                             \
    {                                                                       \
        const float4 v = P;                                                 \
        if (lpf < n) P = p[(size_t)lpf * stride];                           \
        ++lpf;                                                              \
        acc.x += v.x; acc.y += v.y; acc.z += v.z; acc.w += v.w;             \
        const int cw = s_wid[sidx + i];                                     \
        if (i == n - 1 || s_wid[sidx + i + 1] != cw) {                      \
            const int info = g_winfo[b][cw];                                \
            const int lo   = info & 0xffff;                                 \
            const int cnt  = info >> 16;                                    \
            const float inv = 1.0f / (float)cnt;                            \
            float4 r;                                                       \
            r.x = acc.x * inv; r.y = acc.y * inv;                           \
            r.z = acc.z * inv; r.w = acc.w * inv;                           \
            float4* o = out + ((size_t)cw * Bc + b) * (Dc / 4) + t;         \
            if (lo >= base && lo + cnt <= base + CH) {                      \
                *o = r;                                                     \
            } else {                                                        \
                float* of = (float*)o;                                      \
                atomicAdd(of + 0, r.x); atomicAdd(of + 1, r.y);             \
                atomicAdd(of + 2, r.z); atomicAdd(of + 3, r.w);             \
            }                                                               \
            acc = zero;                                                     \
        }                                                                   \
        ++i;                                                                \
    }

    while (i < n) {
        STEP(q0); if (i >= n) break;
        STEP(q1); if (i >= n) break;
        STEP(q2); if (i >= n) break;
        STEP(q3); if (i >= n) break;
        STEP(q4); if (i >= n) break;
        STEP(q5); if (i >= n) break;
        STEP(q6); if (i >= n) break;
        STEP(q7);
    }
#undef STEP
}

// ---------------------------------------------------------------------------
extern "C" void kernel_launch(void* const* d_in, const int* in_sizes, int n_in,
                              void* d_out, int out_size) {
    const float* char_feats = (const float*)d_in[0];
    const int*   word_ids   = (const int*)d_in[1];
    const int*   attn       = (const int*)d_in[2];

    float* out_feats = (float*)d_out;
    float* out_mask  = out_feats + (size_t)Wc * Bc * Dc;

    prep_kernel<<<Bc, Lc>>>(word_ids, attn, (float4*)out_feats, out_mask);
    pool_kernel<<<dim3(NCH, Bc), 64>>>(
        (const float4*)char_feats, word_ids, (float4*)out_feats);
}